// round 12
// baseline (speedup 1.0000x reference)
#include <cuda_runtime.h>

// FOG: stride-2 occupancy downsample of 4M sparse voxels.
// v8: spatial binning. key>>18 = b*512+pz gives exactly 2048 bins of 2^18 keys.
// Each bin's occupancy bitmap is 32KB -> lives in SMEM of one CTA. No global
// 64MB bitmap, no global scan pass, no big clear. Ranks via in-SMEM word scan
// + decoupled lookback over 2048 bin aggregates (bin order == sorted key order).

#define HALF 512
#define NBINS 2048
#define CAP 4096                    // slots per bin (mean ~1953, Poisson)
#define BINMASK ((1u << 18) - 1u)
#define BWORDS 4096                 // u64 words per bin bitmap (32KB)
#define KBT 512                     // threads per kBin CTA
#define WPT (BWORDS / KBT)          // 8 bitmap words per thread
#define PPT (CAP / KBT)             // max 8 points per thread

__device__ unsigned g_slots[NBINS * CAP];   // 32 MB packed (key<<3)|off per bin
__device__ unsigned g_cnt[NBINS];
__device__ unsigned g_status[NBINS];        // lookback: (val<<2)|flag
__device__ unsigned g_ticket;
__device__ unsigned g_total;

// ---- pass A: key/off per point, scatter into bins -------------------------
#define KA_P 4
__global__ void kA(const int4* __restrict__ coords, int n) {
    int base = (blockIdx.x * blockDim.x + threadIdx.x) * KA_P;
    if (base >= n) return;
    int m = n - base; if (m > KA_P) m = KA_P;
    int4 c[KA_P];
#pragma unroll
    for (int j = 0; j < KA_P; j++)
        c[j] = (j < m) ? __ldcs(&coords[base + j]) : make_int4(0, 0, 0, 0);
    unsigned key[KA_P], off[KA_P];
#pragma unroll
    for (int j = 0; j < KA_P; j++) {
        off[j] = (unsigned)((c[j].y & 1) | ((c[j].z & 1) << 1) | ((c[j].w & 1) << 2));
        key[j] = (((unsigned)c[j].x * HALF + (unsigned)(c[j].w >> 1)) * HALF
                  + (unsigned)(c[j].z >> 1)) * HALF + (unsigned)(c[j].y >> 1);
    }
#pragma unroll
    for (int j = 0; j < KA_P; j++) {
        if (j >= m) continue;
        unsigned bin = key[j] >> 18;
        unsigned pos = atomicAdd(&g_cnt[bin], 1u);   // 2048 hot counters
        if (pos < CAP) g_slots[bin * CAP + pos] = (key[j] << 3) | off[j];
    }
}

// ---- per-bin: SMEM bitmap + scan + lookback + coalesced emit --------------
__global__ void __launch_bounds__(KBT) kBin(const float* __restrict__ kw,
                                            float4* __restrict__ cout,
                                            float* __restrict__ feats) {
    extern __shared__ unsigned char smem[];
    unsigned long long* bm = reinterpret_cast<unsigned long long*>(smem);  // 32KB
    unsigned* wpre = reinterpret_cast<unsigned*>(smem + 32768);            // 16KB
    float*    lf   = reinterpret_cast<float*>(smem + 49152);               // 16KB
    __shared__ unsigned s_bin, s_base;
    __shared__ unsigned s_warp[KBT / 32];

    const unsigned tid = threadIdx.x;
    if (tid == 0) s_bin = atomicAdd(&g_ticket, 1u);
    __syncthreads();
    const unsigned bin = s_bin;
    unsigned cnt = g_cnt[bin]; if (cnt > CAP) cnt = CAP;

    for (unsigned w = tid; w < BWORDS; w += KBT) bm[w] = 0ull;
    __syncthreads();

    // mark bits; keep packed points in registers for the feats pass
    unsigned preg[PPT];
    int np = 0;
    for (unsigned j = tid; j < cnt; j += KBT) {
        unsigned p = __ldg(&g_slots[bin * CAP + j]);
        preg[np++] = p;
        unsigned low = (p >> 3) & BINMASK;
        atomicOr(&bm[low >> 6], 1ull << (low & 63u));
    }
    __syncthreads();

    // scan 4096 words (8 per thread)
    const unsigned wbase = tid * WPT;
    unsigned pc[WPT], s = 0;
#pragma unroll
    for (int j = 0; j < WPT; j++) { pc[j] = (unsigned)__popcll(bm[wbase + j]); s += pc[j]; }
    const unsigned lane = tid & 31u, wid = tid >> 5;
    unsigned inc = s;
#pragma unroll
    for (int d = 1; d < 32; d <<= 1) {
        unsigned x = __shfl_up_sync(0xffffffffu, inc, d);
        if (lane >= (unsigned)d) inc += x;
    }
    if (lane == 31) s_warp[wid] = inc;
    __syncthreads();
    if (tid < KBT / 32) {
        unsigned v = s_warp[tid];
#pragma unroll
        for (int d = 1; d < KBT / 32; d <<= 1) {
            unsigned x = __shfl_up_sync(0xffffu, v, d);
            if (tid >= (unsigned)d) v += x;
        }
        s_warp[tid] = v;
    }
    __syncthreads();
    const unsigned threadExcl = (wid ? s_warp[wid - 1] : 0u) + (inc - s);
    const unsigned agg = s_warp[KBT / 32 - 1];
    {
        unsigned run = threadExcl;
#pragma unroll
        for (int j = 0; j < WPT; j++) { wpre[wbase + j] = run; run += pc[j]; }
    }

    // publish aggregate + decoupled lookback for global rank base
    if (tid == 0) {
        if (bin == 0) {
            atomicExch(&g_status[0], (agg << 2) | 2u);
            s_base = 0u;
        } else {
            atomicExch(&g_status[bin], (agg << 2) | 1u);
        }
    }
    if (wid == 0 && bin > 0) {
        unsigned excl = 0;
        int look = (int)bin - 1;
        for (;;) {
            int idx = look - (int)lane;
            unsigned stv;
            do {
                stv = (idx >= 0) ? *(volatile unsigned*)&g_status[idx] : 2u;
            } while (__any_sync(0xffffffffu, (stv & 3u) == 0u));
            unsigned incMask = __ballot_sync(0xffffffffu, (stv & 3u) == 2u);
            if (incMask) {
                int firstInc = __ffs(incMask) - 1;
                unsigned contrib = (lane <= (unsigned)firstInc && idx >= 0) ? (stv >> 2) : 0u;
#pragma unroll
                for (int d = 16; d; d >>= 1) contrib += __shfl_down_sync(0xffffffffu, contrib, d);
                excl += __shfl_sync(0xffffffffu, contrib, 0);
                break;
            } else {
                unsigned contrib = (idx >= 0) ? (stv >> 2) : 0u;
#pragma unroll
                for (int d = 16; d; d >>= 1) contrib += __shfl_down_sync(0xffffffffu, contrib, d);
                excl += __shfl_sync(0xffffffffu, contrib, 0);
                look -= 32;
            }
        }
        if (lane == 0) {
            atomicExch(&g_status[bin], ((excl + agg) << 2) | 2u);
            s_base = excl;
            if (bin == NBINS - 1) g_total = excl + agg;
        }
    }
    __syncthreads();
    const unsigned gbase = s_base;

    // zero local feats, accumulate contributions in SMEM
    for (unsigned r = tid; r < agg; r += KBT) lf[r] = 0.f;
    __syncthreads();
    {
        int idx = 0;
        for (unsigned j = tid; j < cnt; j += KBT) {
            unsigned p = preg[idx++];
            unsigned low = (p >> 3) & BINMASK, off = p & 7u;
            unsigned w = low >> 6, b = low & 63u;
            unsigned r = wpre[w] + (unsigned)__popcll(bm[w] & ((1ull << b) - 1ull));
            atomicAdd(&lf[r], (float)(1u << off) * __ldg(&kw[off]));
        }
    }
    __syncthreads();

    // coalesced feats write
    for (unsigned r = tid; r < agg; r += KBT) __stcs(&feats[gbase + r], lf[r]);

    // emit compacted sorted coords (each thread walks its 8 words)
#pragma unroll
    for (int j = 0; j < WPT; j++) {
        unsigned long long word = bm[wbase + j];
        unsigned r = gbase + wpre[wbase + j];
        unsigned kb = (bin << 18) | ((wbase + j) << 6);
        while (word) {
            unsigned b = (unsigned)__ffsll((long long)word) - 1u;
            word &= word - 1ull;
            unsigned key = kb + b;
            __stcs(&cout[r], make_float4((float)(key >> 27),
                                         (float)(key & 511u),
                                         (float)((key >> 9) & 511u),
                                         (float)((key >> 18) & 511u)));
            r++;
        }
    }
}

// ---- pad tail + clear tiny state ------------------------------------------
__global__ void kF(float4* __restrict__ cout, float* __restrict__ feats, int n) {
    int i = blockIdx.x * blockDim.x + threadIdx.x;
    if (i < NBINS) { g_cnt[i] = 0u; g_status[i] = 0u; }
    if (i == 0) g_ticket = 0u;
    if (i >= n) return;
    if ((unsigned)i >= g_total) {
        __stcs(&cout[i], make_float4(-1.f, -1.f, -1.f, -1.f));
        feats[i] = 0.f;
    }
}

extern "C" void kernel_launch(void* const* d_in, const int* in_sizes, int n_in,
                              void* d_out, int out_size) {
    const int4*  coords = (const int4*)d_in[0];
    const float* kw     = (const float*)d_in[1];
    float* out = (float*)d_out;
    int n = in_sizes[0] / 4;                 // number of points
    float* feats = out + (size_t)4 * n;      // layout: coords (N,4) then feats (N,1)

    const int TB = 256;
    kA<<<(n + TB * KA_P - 1) / (TB * KA_P), TB>>>(coords, n);

    static int smemSet = 0;
    if (!smemSet) {
        cudaFuncSetAttribute(kBin, cudaFuncAttributeMaxDynamicSharedMemorySize, 65536);
        smemSet = 1;
    }
    kBin<<<NBINS, KBT, 65536>>>(kw, (float4*)out, feats);
    kF<<<(n + TB - 1) / TB, TB>>>((float4*)out, feats, n);
}

// round 13
// speedup vs baseline: 2.6445x; 2.6445x over previous
#include <cuda_runtime.h>

// FOG: stride-2 occupancy downsample of 4M sparse voxels.
// v9 = v4 (best: 64MB word bitmap + per-4-word prefix + lookback scan) with:
//  - kB at KB_P=4 for doubled gather MLP
//  - kA issues REDG atomics as early as possible
//  - feats zeroing folded into kA; state cleared by cudaMemsetAsync

#define HALF 512
#define NWORDS (1u << 23)             // 2^29 keys / 64 bits per word (64 MB)
#define TILE_T 512
#define TILE_I 8
#define TILE_WORDS (TILE_T * TILE_I)  // 4096 words per tile
#define NTILES (NWORDS / TILE_WORDS)  // 2048
#define MAXN 4000000

// One fused clearable state region: [bits | status | ticket]
#define STATE_U64 (NWORDS + (NTILES + 1) / 2 + 1)
__device__ unsigned long long g_state[STATE_U64];
__device__ unsigned int g_prefix4[NWORDS / 4];  // 8.4 MB: rank at each 4-word group
__device__ unsigned int g_packed[MAXN];         // 16 MB per-point (key<<3)|off
__device__ unsigned int g_total;

__device__ __forceinline__ unsigned long long* bitsPtr() { return g_state; }
__device__ __forceinline__ unsigned* statusPtr() { return (unsigned*)(g_state + NWORDS); }
__device__ __forceinline__ unsigned* ticketPtr() { return (unsigned*)(g_state + NWORDS + (NTILES + 1) / 2); }

// ---- pass A: zero feats + key/off per point + mark bitmap (REDG early) ----
#define KA_P 4
__global__ void kA(const int4* __restrict__ coords, float* __restrict__ feats, int n) {
    int base = (blockIdx.x * blockDim.x + threadIdx.x) * KA_P;
    if (base >= n) return;
    int m = n - base; if (m > KA_P) m = KA_P;
    if (m == KA_P) {
        *reinterpret_cast<float4*>(&feats[base]) = make_float4(0.f, 0.f, 0.f, 0.f);
    } else {
        for (int j = 0; j < m; j++) feats[base + j] = 0.f;
    }
    int4 c[KA_P];
#pragma unroll
    for (int j = 0; j < KA_P; j++)
        c[j] = (j < m) ? __ldcs(&coords[base + j]) : make_int4(0, 0, 0, 0);
    unsigned key[KA_P], off[KA_P];
#pragma unroll
    for (int j = 0; j < KA_P; j++) {
        off[j] = (unsigned)((c[j].y & 1) | ((c[j].z & 1) << 1) | ((c[j].w & 1) << 2));
        key[j] = (((unsigned)c[j].x * HALF + (unsigned)(c[j].w >> 1)) * HALF
                  + (unsigned)(c[j].z >> 1)) * HALF + (unsigned)(c[j].y >> 1);
        // atomics are the long pole: issue each as soon as its key is ready
        if (j < m) atomicOr(&bitsPtr()[key[j] >> 6], 1ull << (key[j] & 63));  // REDG
    }
#pragma unroll
    for (int j = 0; j < KA_P; j++)
        if (j < m) __stcs(&g_packed[base + j], (key[j] << 3) | off[j]);
}

// ---- fused scan + compact: decoupled lookback -----------------------------
__global__ void __launch_bounds__(TILE_T) kScan(float4* __restrict__ cout) {
    __shared__ unsigned s_tile;
    __shared__ unsigned s_warpsum[TILE_T / 32];
    __shared__ unsigned s_excl;

    if (threadIdx.x == 0) s_tile = atomicAdd(ticketPtr(), 1u);
    __syncthreads();
    const unsigned tile = s_tile;
    const unsigned base = tile * TILE_WORDS + threadIdx.x * TILE_I;

    unsigned long long words[TILE_I];
    {
        const ulonglong2* p = reinterpret_cast<const ulonglong2*>(&bitsPtr()[base]);
#pragma unroll
        for (int j = 0; j < TILE_I / 2; j++) {
            ulonglong2 v = p[j];                  // plain load: keep bits L2-resident for kB
            words[2 * j] = v.x; words[2 * j + 1] = v.y;
        }
    }
    unsigned pc[TILE_I], s = 0;
#pragma unroll
    for (int j = 0; j < TILE_I; j++) { pc[j] = (unsigned)__popcll(words[j]); s += pc[j]; }

    const unsigned lane = threadIdx.x & 31u, wid = threadIdx.x >> 5;
    unsigned inc = s;
#pragma unroll
    for (int d = 1; d < 32; d <<= 1) {
        unsigned x = __shfl_up_sync(0xffffffffu, inc, d);
        if (lane >= (unsigned)d) inc += x;
    }
    if (lane == 31) s_warpsum[wid] = inc;
    __syncthreads();
    if (threadIdx.x < TILE_T / 32) {
        unsigned v = s_warpsum[threadIdx.x];
#pragma unroll
        for (int d = 1; d < TILE_T / 32; d <<= 1) {
            unsigned x = __shfl_up_sync((1u << (TILE_T / 32)) - 1u, v, d);
            if (threadIdx.x >= (unsigned)d) v += x;
        }
        s_warpsum[threadIdx.x] = v;
    }
    __syncthreads();
    const unsigned wordExcl = (wid ? s_warpsum[wid - 1] : 0u) + (inc - s);
    const unsigned tileAgg  = s_warpsum[TILE_T / 32 - 1];

    unsigned* status = statusPtr();
    if (threadIdx.x == 0) {
        if (tile == 0) {
            atomicExch(&status[0], (tileAgg << 2) | 2u);
            s_excl = 0u;
            if (NTILES == 1) g_total = tileAgg;
        } else {
            atomicExch(&status[tile], (tileAgg << 2) | 1u);
        }
    }

    if (wid == 0 && tile > 0) {
        unsigned excl = 0;
        int look = (int)tile - 1;
        for (;;) {
            int idx = look - (int)lane;
            unsigned stv;
            do {
                stv = (idx >= 0) ? *(volatile unsigned*)&status[idx] : 2u;
            } while (__any_sync(0xffffffffu, (stv & 3u) == 0u));
            unsigned incMask = __ballot_sync(0xffffffffu, (stv & 3u) == 2u);
            if (incMask) {
                int firstInc = __ffs(incMask) - 1;
                unsigned contrib = (lane <= (unsigned)firstInc && idx >= 0) ? (stv >> 2) : 0u;
#pragma unroll
                for (int d = 16; d; d >>= 1) contrib += __shfl_down_sync(0xffffffffu, contrib, d);
                excl += __shfl_sync(0xffffffffu, contrib, 0);
                break;
            } else {
                unsigned contrib = (idx >= 0) ? (stv >> 2) : 0u;
#pragma unroll
                for (int d = 16; d; d >>= 1) contrib += __shfl_down_sync(0xffffffffu, contrib, d);
                excl += __shfl_sync(0xffffffffu, contrib, 0);
                look -= 32;
            }
        }
        if (lane == 0) {
            atomicExch(&status[tile], ((excl + tileAgg) << 2) | 2u);
            s_excl = excl;
            if (tile == NTILES - 1) g_total = excl + tileAgg;
        }
    }
    __syncthreads();

    unsigned rank = s_excl + wordExcl;

    {
        unsigned g4 = base >> 2;
        g_prefix4[g4]     = rank;
        g_prefix4[g4 + 1] = rank + pc[0] + pc[1] + pc[2] + pc[3];
    }

    unsigned r = rank;
#pragma unroll
    for (int j = 0; j < TILE_I; j++) {
        unsigned long long word = words[j];
        unsigned keybase = (base + j) << 6;
        while (word) {
            unsigned b = (unsigned)__ffsll((long long)word) - 1u;
            word &= word - 1ull;
            unsigned key = keybase + b;
            float4 v = make_float4((float)(key >> 27),
                                   (float)(key & 511u),
                                   (float)((key >> 9) & 511u),
                                   (float)((key >> 18) & 511u));
            __stcs(&cout[r], v);
            r++;
        }
    }
}

// ---- pass B: rank gather + feats scatter-add + pad (4 pts/thread) ---------
#define KB_P 4
__global__ void kB(const float* __restrict__ kw, float* __restrict__ feats,
                   float4* __restrict__ cout, int n) {
    int base = (blockIdx.x * blockDim.x + threadIdx.x) * KB_P;
    if (base >= n) return;
    int m = n - base; if (m > KB_P) m = KB_P;
    unsigned p[KB_P];
#pragma unroll
    for (int j = 0; j < KB_P; j++)
        p[j] = (j < m) ? __ldcs(&g_packed[base + j]) : 0u;
    ulonglong2 lo[KB_P], hi[KB_P];
    unsigned pre[KB_P];
#pragma unroll
    for (int j = 0; j < KB_P; j++) {
        unsigned g4 = (p[j] >> 3) >> 8;  // key>>6>>2
        const ulonglong2* gp = reinterpret_cast<const ulonglong2*>(&bitsPtr()[(size_t)g4 << 2]);
        lo[j] = __ldg(gp);
        hi[j] = __ldg(gp + 1);
        pre[j] = __ldg(&g_prefix4[g4]);
    }
    unsigned total = g_total;
#pragma unroll
    for (int j = 0; j < KB_P; j++) {
        if (j >= m) continue;
        unsigned key = p[j] >> 3;
        unsigned off = p[j] & 7u;
        unsigned b = key & 63u;
        unsigned wi = (key >> 6) & 3u;
        unsigned r = pre[j];
        if (wi > 0) r += (unsigned)__popcll(lo[j].x);
        if (wi > 1) r += (unsigned)__popcll(lo[j].y);
        if (wi > 2) r += (unsigned)__popcll(hi[j].x);
        unsigned long long wsel = (wi == 0) ? lo[j].x : (wi == 1) ? lo[j].y
                                 : (wi == 2) ? hi[j].x : hi[j].y;
        r += (unsigned)__popcll(wsel & ((1ull << b) - 1ull));
        float contrib = (float)(1u << off) * __ldg(&kw[off]);
        atomicAdd(&feats[r], contrib);  // REDG
        if ((unsigned)(base + j) >= total)
            __stcs(&cout[base + j], make_float4(-1.f, -1.f, -1.f, -1.f));
    }
}

extern "C" void kernel_launch(void* const* d_in, const int* in_sizes, int n_in,
                              void* d_out, int out_size) {
    const int4*  coords = (const int4*)d_in[0];
    const float* kw     = (const float*)d_in[1];
    float* out = (float*)d_out;
    int n = in_sizes[0] / 4;                 // number of points
    float* feats = out + (size_t)4 * n;      // layout: coords (N,4) then feats (N,1)

    const int TB = 256;
    kA<<<(n + TB * KA_P - 1) / (TB * KA_P), TB>>>(coords, feats, n);
    kScan<<<NTILES, TILE_T>>>((float4*)out);
    kB<<<(n + TB * KB_P - 1) / (TB * KB_P), TB>>>(kw, feats, (float4*)out, n);

    // clear bitmap + lookback status + ticket for the next graph replay
    void* statePtr = nullptr;
    cudaGetSymbolAddress(&statePtr, g_state);
    cudaMemsetAsync(statePtr, 0, (size_t)STATE_U64 * sizeof(unsigned long long), 0);
}